// round 7
// baseline (speedup 1.0000x reference)
#include <cuda_runtime.h>
#include <cstdint>

// ---------------- problem constants ----------------
constexpr int NEg   = 100000;
constexpr int NAg   = 5000;
constexpr int DDg   = 512;
constexpr int DTg   = 64;
constexpr int NCBF  = 16;

constexpr float INV_SQRT2 = 0.70710678118654752f;
constexpr float ACT_SCALE = 1.0f / 0.6f;

// ---------------- scratch pool ----------------
constexpr size_t NE512 = (size_t)NEg * DDg;
constexpr size_t NA512 = (size_t)NAg * DDg;

constexpr size_t OFF_XCA  = 0;
constexpr size_t OFF_TMP  = OFF_XCA  + NE512;
constexpr size_t OFF_UP   = OFF_TMP  + NE512;
constexpr size_t OFF_M    = OFF_UP   + NE512;
constexpr size_t OFF_DWN  = OFF_M    + NE512;
constexpr size_t OFF_XB   = OFF_DWN  + (size_t)NEg * DTg;
constexpr size_t OFF_T2   = OFF_XB   + (size_t)NEg * DTg;
constexpr size_t OFF_WBP  = OFF_T2   + (size_t)NEg * NCBF * DTg;
constexpr size_t OFF_A1   = OFF_WBP  + (size_t)NCBF * DTg * DTg;
constexpr size_t OFF_A2   = OFF_A1   + NA512;
constexpr size_t OFF_A3   = OFF_A2   + NA512;
constexpr size_t OFF_MT   = OFF_A3   + NA512;
constexpr size_t OFF_XCAT = OFF_MT   + NE512;
constexpr size_t OFF_MBT  = OFF_XCAT + NE512;
constexpr size_t OFF_A1T  = OFF_MBT  + NE512;
constexpr size_t OFF_A2T  = OFF_A1T  + NA512;
constexpr size_t OFF_OHT  = OFF_A2T  + NA512;
constexpr size_t OFF_R3T  = OFF_OHT  + NA512;
constexpr size_t OFF_RHT  = OFF_R3T  + (size_t)NEg * 16;
constexpr size_t OFF_WTS  = OFF_RHT  + (size_t)NEg * 16;
constexpr size_t WTS_SZ   = 8u * 1024 * 1024;
constexpr size_t POOL_TOTAL = OFF_WTS + WTS_SZ;

__device__ __align__(256) float g_pool[POOL_TOTAL];

// ---------------- helpers ----------------
__device__ __forceinline__ float scaled_silu(float x) {
    return x * (1.0f / (1.0f + __expf(-x))) * ACT_SCALE;
}
__device__ __forceinline__ uint32_t f2tf32(float x) {
    uint32_t u;
    asm("cvt.rna.tf32.f32 %0, %1;" : "=r"(u) : "f"(x));
    return u;
}
__device__ __forceinline__ float tf32f(float x) { return __uint_as_float(f2tf32(x)); }

__device__ __forceinline__ void mma_tf32(float4& d, const uint32_t a[4], const uint32_t b[2]) {
    asm volatile(
        "mma.sync.aligned.m16n8k8.row.col.f32.tf32.tf32.f32 "
        "{%0,%1,%2,%3}, {%4,%5,%6,%7}, {%8,%9}, {%0,%1,%2,%3};"
        : "+f"(d.x), "+f"(d.y), "+f"(d.z), "+f"(d.w)
        : "r"(a[0]), "r"(a[1]), "r"(a[2]), "r"(a[3]), "r"(b[0]), "r"(b[1]));
}
__device__ __forceinline__ void cp16(uint32_t smem_dst, const float* gsrc, int szbytes) {
    asm volatile("cp.async.cg.shared.global [%0], [%1], 16, %2;"
                 :: "r"(smem_dst), "l"(gsrc), "r"(szbytes));
}
__device__ __forceinline__ void cp_commit() { asm volatile("cp.async.commit_group;"); }
template <int N> __device__ __forceinline__ void cp_wait() {
    asm volatile("cp.async.wait_group %0;" :: "n"(N));
}

// ---------------- tf32 tensor-core GEMM (inputs pre-rounded to tf32 bits) ----------------
enum { F_ACT = 1, F_MUL = 2, F_ADD1 = 4, F_ADD2 = 8, F_CAT = 16, F_OUT_TF32 = 32, F_C_TF32 = 64 };

// BK=16 stages: As[128][20] + Bs[16][136] floats
#define SA 20
#define SB 136
constexpr int NSTAGE = 4;
constexpr int AS_BYTES = 128 * SA * 4;                 // 10240
constexpr int BS_BYTES = 16 * SB * 4;                  // 8704
constexpr int STAGE_BYTES = AS_BYTES + BS_BYTES;       // 18944
constexpr int SMEM_DYN = NSTAGE * STAGE_BYTES;         // 75776

__device__ __forceinline__ void epi2(float* C, float* Ct, size_t idx, float vx, float vy, int flags,
                                     const float* Emul, const float* Add1, float c1,
                                     const float* Add2, float c2) {
    if (flags & F_ACT)  { vx = scaled_silu(vx);       vy = scaled_silu(vy); }
    if (flags & F_MUL)  { vx *= Emul[idx];            vy *= Emul[idx + 1]; }
    if (flags & F_ADD1) { vx = (Add1[idx] + vx) * c1; vy = (Add1[idx + 1] + vy) * c1; }
    if (flags & F_ADD2) { vx = (vx + Add2[idx]) * c2; vy = (vy + Add2[idx + 1]) * c2; }
    if (flags & F_OUT_TF32) { Ct[idx] = tf32f(vx); Ct[idx + 1] = tf32f(vy); }
    if (flags & F_C_TF32)   { vx = tf32f(vx); vy = tf32f(vy); }
    C[idx] = vx; C[idx + 1] = vy;
}

__global__ __launch_bounds__(128, 2)
void mma_gemm_kernel(const float* __restrict__ A, const float* __restrict__ B, float* __restrict__ C,
                     float* __restrict__ Ct,
                     int M, int N, int K, int flags,
                     const float* __restrict__ Emul,
                     const float* __restrict__ Add1, float c1,
                     const float* __restrict__ Add2, float c2,
                     const float* __restrict__ Hg, const int* __restrict__ idxs,
                     const int* __restrict__ idxt, const float* __restrict__ Mg)
{
    extern __shared__ __align__(16) char dyn_smem[];

    const int t = threadIdx.x;            // 128 threads
    const int lane = t & 31;
    const int warp = t >> 5;
    const int wm = (warp >> 1) * 64;      // 2 warps in M
    const int wn = (warp & 1) * 64;       // 2 warps in N
    const int rowC0 = blockIdx.y * 128;
    const int colC0 = blockIdx.x * 128;

    const uint32_t smem0 = (uint32_t)__cvta_generic_to_shared(dyn_smem);

    // A loads: thread t -> row t, all 16 k (4 chunks of 4 floats)
    const int arow = rowC0 + t;
    const bool aok = arow < M;
    int isg = 0, itg = 0;
    if ((flags & F_CAT) && aok) { isg = idxs[arow]; itg = idxt[arow]; }
    const uint32_t a_dst = smem0 + (uint32_t)(t * SA) * 4;

    // B loads: thread t -> k-row t>>3 (0..15), col chunk (t&7)*16 (4 chunks)
    const int bk = t >> 3;
    const int bnc = (t & 7) * 16;
    const uint32_t b_dst = smem0 + AS_BYTES + (uint32_t)(bk * SB + bnc) * 4;

    float4 acc[4][8];
#pragma unroll
    for (int i = 0; i < 4; i++)
#pragma unroll
        for (int j = 0; j < 8; j++) acc[i][j] = make_float4(0.f, 0.f, 0.f, 0.f);

    auto loadTile = [&](int s, int k0) {
        const uint32_t soff = (uint32_t)s * STAGE_BYTES;
        // ---- A ----
        const float* ap;
        if (!(flags & F_CAT)) {
            ap = A + (size_t)(aok ? arow : 0) * K + k0;
        } else {
            if (k0 < 512)       ap = Hg + (size_t)isg * 512 + k0;
            else if (k0 < 1024) ap = Hg + (size_t)itg * 512 + (k0 - 512);
            else                ap = Mg + (size_t)(aok ? arow : 0) * 512 + (k0 - 1024);
        }
#pragma unroll
        for (int ch = 0; ch < 4; ch++) {
            const bool ok = aok && (k0 + ch * 4) < K;
            cp16(a_dst + soff + 16u * ch, ok ? (ap + 4 * ch) : A, ok ? 16 : 0);
        }
        // ---- B ----
        const bool kok = (k0 + bk) < K;
        const float* bp = B + (size_t)(k0 + bk) * N + colC0 + bnc;
#pragma unroll
        for (int ch = 0; ch < 4; ch++) {
            const bool ok = kok && (colC0 + bnc + ch * 4) < N;
            cp16(b_dst + soff + 16u * ch, ok ? (bp + 4 * ch) : B, ok ? 16 : 0);
        }
    };

    auto computeTile = [&](int s) {
        const uint32_t* Au = (const uint32_t*)(dyn_smem + (size_t)s * STAGE_BYTES);
        const uint32_t* Bu = (const uint32_t*)(dyn_smem + (size_t)s * STAGE_BYTES + AS_BYTES);
#pragma unroll
        for (int k8 = 0; k8 < 2; k8++) {
            const int c = k8 * 8 + (lane & 3);
            uint32_t af[4][4];
            uint32_t bf[8][2];
            const int rbase = wm + (lane >> 2);
#pragma unroll
            for (int mt = 0; mt < 4; mt++) {
                const int r = rbase + mt * 16;
                af[mt][0] = Au[r * SA + c];
                af[mt][1] = Au[(r + 8) * SA + c];
                af[mt][2] = Au[r * SA + c + 4];
                af[mt][3] = Au[(r + 8) * SA + c + 4];
            }
            const int nbase = wn + (lane >> 2);
#pragma unroll
            for (int nt = 0; nt < 8; nt++) {
                const int n = nbase + nt * 8;
                bf[nt][0] = Bu[c * SB + n];
                bf[nt][1] = Bu[(c + 4) * SB + n];
            }
#pragma unroll
            for (int mt = 0; mt < 4; mt++)
#pragma unroll
                for (int nt = 0; nt < 8; nt++)
                    mma_tf32(acc[mt][nt], af[mt], bf[nt]);
        }
    };

    const int nK = (K + 15) >> 4;
    const int pre = nK < (NSTAGE - 1) ? nK : (NSTAGE - 1);
    for (int s = 0; s < pre; s++) { loadTile(s, s * 16); cp_commit(); }

    for (int i = 0; i < nK; ++i) {
        const int rem = nK - 1 - i;
        if (rem >= 2)      cp_wait<2>();
        else if (rem == 1) cp_wait<1>();
        else               cp_wait<0>();
        __syncthreads();
        // refilled stage (i-1)&3 has no pending consumers after the sync above
        if (i + NSTAGE - 1 < nK) { loadTile((i + NSTAGE - 1) & 3, (i + NSTAGE - 1) * 16); cp_commit(); }
        computeTile(i & 3);
    }

    // epilogue (warp tile 64x64)
#pragma unroll
    for (int mt = 0; mt < 4; mt++) {
        const int r = rowC0 + wm + mt * 16 + (lane >> 2);
#pragma unroll
        for (int nt = 0; nt < 8; nt++) {
            const int cc = colC0 + wn + nt * 8 + (lane & 3) * 2;
            if (cc >= N) continue;
            const float4 v = acc[mt][nt];
            if (r < M)
                epi2(C, Ct, (size_t)r * N + cc, v.x, v.y, flags, Emul, Add1, c1, Add2, c2);
            if (r + 8 < M)
                epi2(C, Ct, (size_t)(r + 8) * N + cc, v.z, v.w, flags, Emul, Add1, c1, Add2, c2);
        }
    }
}

// ---------------- elementwise tf32 conversion ----------------
__global__ void conv_tf32_kernel(const float* __restrict__ src, float* __restrict__ dst, int n4) {
    const int i = blockIdx.x * blockDim.x + threadIdx.x;
    if (i >= n4) return;
    float4 v = ((const float4*)src)[i];
    v.x = tf32f(v.x); v.y = tf32f(v.y); v.z = tf32f(v.z); v.w = tf32f(v.w);
    ((float4*)dst)[i] = v;
}

// ---------------- triplet tmp2 (writes tf32) ----------------
__global__ void triplet_tmp2_kernel(const float* __restrict__ down,
                                    const int* __restrict__ id3_ba,
                                    const float* __restrict__ sph,
                                    const float* __restrict__ rbfw1,
                                    float* __restrict__ t2)
{
    __shared__ int   sIdx[256];
    __shared__ float sS[16 * 112];
    __shared__ float sR[16 * 112];

    const int tid = threadIdx.x;
    const int e0 = blockIdx.x * 16;

    sIdx[tid] = id3_ba[(size_t)e0 * 16 + tid];
    for (int r = tid; r < 16 * 112; r += 256) {
        sS[r] = sph  [(size_t)e0 * 112 + r];
        sR[r] = rbfw1[(size_t)e0 * 112 + r];
    }
    __syncthreads();

    const int team = tid >> 4;
    const int j = tid & 15;
    const int edge = e0 + team;

    float4 G[16];
#pragma unroll
    for (int k = 0; k < 16; k++) {
        const int row = sIdx[team * 16 + k];
        G[k] = *(const float4*)(down + (size_t)row * 64 + j * 4);
    }

    float4 t1[7];
#pragma unroll
    for (int s = 0; s < 7; s++) {
        float4 a = make_float4(0.f, 0.f, 0.f, 0.f);
#pragma unroll
        for (int k = 0; k < 16; k++) {
            const float f = sS[team * 112 + s * 16 + k];
            a.x = fmaf(f, G[k].x, a.x); a.y = fmaf(f, G[k].y, a.y);
            a.z = fmaf(f, G[k].z, a.z); a.w = fmaf(f, G[k].w, a.w);
        }
        t1[s] = a;
    }

    float4* out = (float4*)(t2 + (size_t)edge * 1024);
#pragma unroll
    for (int i = 0; i < 16; i++) {
        float4 a = make_float4(0.f, 0.f, 0.f, 0.f);
#pragma unroll
        for (int s = 0; s < 7; s++) {
            const float f = sR[team * 112 + i * 7 + s];
            a.x = fmaf(f, t1[s].x, a.x); a.y = fmaf(f, t1[s].y, a.y);
            a.z = fmaf(f, t1[s].z, a.z); a.w = fmaf(f, t1[s].w, a.w);
        }
        a.x = tf32f(a.x); a.y = tf32f(a.y); a.z = tf32f(a.z); a.w = tf32f(a.w);
        out[i * 16 + j] = a;
    }
}

// W_bil[e,i,o] -> WBP[i*64+e, o]  (tf32, [K][N] layout)
__global__ void permute_wbil_kernel(const float* __restrict__ wb, float* __restrict__ out) {
    const int idx = blockIdx.x * blockDim.x + threadIdx.x;
    const int o = idx & 63;
    const int i = (idx >> 6) & 15;
    const int e = idx >> 10;
    out[((size_t)(i * 64 + e)) * 64 + o] = tf32f(wb[((size_t)(e * 16 + i)) * 64 + o]);
}

// x = (xca_skip + (up + ac[id_swap])*c)*c  -> fp32 XCA + tf32 XCAt
__global__ void combine_x_kernel(float* xca, float* xcat, const float* __restrict__ up,
                                 const float* __restrict__ ac, const int* __restrict__ id_swap) {
    const int idx = blockIdx.x * blockDim.x + threadIdx.x;
    const int e = idx >> 7;
    const int c = idx & 127;
    const int es = id_swap[e];
    float4 a = ((const float4*)up)[idx];
    float4 b = ((const float4*)ac)[(size_t)es * 128 + c];
    float4 x = ((float4*)xca)[idx];
    x.x = (x.x + (a.x + b.x) * INV_SQRT2) * INV_SQRT2;
    x.y = (x.y + (a.y + b.y) * INV_SQRT2) * INV_SQRT2;
    x.z = (x.z + (a.z + b.z) * INV_SQRT2) * INV_SQRT2;
    x.w = (x.w + (a.w + b.w) * INV_SQRT2) * INV_SQRT2;
    ((float4*)xca)[idx] = x;
    float4 xt;
    xt.x = tf32f(x.x); xt.y = tf32f(x.y); xt.z = tf32f(x.z); xt.w = tf32f(x.w);
    ((float4*)xcat)[idx] = xt;
}

// segment-sum: out[idx_t[e]] += m[e]*r2[e]
__global__ void scatter_atoms_kernel(const float* __restrict__ m, const float* __restrict__ r2,
                                     const int* __restrict__ idx_t, float* out) {
    const int idx = blockIdx.x * blockDim.x + threadIdx.x;
    const int e = idx >> 7;
    const int c = idx & 127;
    const int t = idx_t[e];
    float4 a = ((const float4*)m)[idx];
    float4 b = ((const float4*)r2)[idx];
    float* dst = out + (size_t)t * 512 + c * 4;
    atomicAdd(dst + 0, a.x * b.x);
    atomicAdd(dst + 1, a.y * b.y);
    atomicAdd(dst + 2, a.z * b.z);
    atomicAdd(dst + 3, a.w * b.w);
}

// ---------------- host orchestration ----------------
static void run_gemm(const float* A, const float* B, float* C, int M, int N, int K, int flags,
                     float* Ct = nullptr,
                     const float* E = nullptr,
                     const float* Ad1 = nullptr, float c1 = 1.f,
                     const float* Ad2 = nullptr, float c2 = 1.f,
                     const float* Hg = nullptr, const int* isx = nullptr,
                     const int* itx = nullptr, const float* Mg = nullptr)
{
    static bool attr_set = false;
    if (!attr_set) {
        cudaFuncSetAttribute(mma_gemm_kernel, cudaFuncAttributeMaxDynamicSharedMemorySize, SMEM_DYN);
        attr_set = true;
    }
    dim3 grid((N + 127) / 128, (M + 127) / 128);
    mma_gemm_kernel<<<grid, 128, SMEM_DYN>>>(A, B, C, Ct, M, N, K, flags,
                                             E, Ad1, c1, Ad2, c2, Hg, isx, itx, Mg);
}
static void run_conv(const float* src, float* dst, size_t n) {
    const int n4 = (int)(n / 4);
    conv_tf32_kernel<<<(n4 + 255) / 256, 256>>>(src, dst, n4);
}

extern "C" void kernel_launch(void* const* d_in, const int* in_sizes, int n_in,
                              void* d_out, int out_size)
{
    const float* h_in    = (const float*)d_in[0];
    const float* m_in    = (const float*)d_in[1];
    const float* rbf3    = (const float*)d_in[2];
    const float* rbf_w1  = (const float*)d_in[3];
    const float* sph     = (const float*)d_in[4];
    const float* rbf_h   = (const float*)d_in[5];
    const int*   id3_ba  = (const int*)d_in[6];
    const int*   id_swap = (const int*)d_in[9];
    const int*   idx_s   = (const int*)d_in[10];
    const int*   idx_t   = (const int*)d_in[11];
    const float* W_dense_ca = (const float*)d_in[12];
    const float* W_ba    = (const float*)d_in[13];
    const float* W_rbf3  = (const float*)d_in[14];
    const float* W_down  = (const float*)d_in[15];
    const float* W_bil   = (const float*)d_in[16];
    const float* W_up_ca = (const float*)d_in[17];
    const float* W_up_ac = (const float*)d_in[18];
    const float* W_bs    = (const float*)d_in[19];
    const float* W_as    = (const float*)d_in[20];
    const float* W_au_rbf= (const float*)d_in[21];
    const float* W_au_d1 = (const float*)d_in[22];
    const float* W_au_res= (const float*)d_in[23];
    const float* W_cat   = (const float*)d_in[24];
    const float* W_res_m = (const float*)d_in[25];

    float* pool = nullptr;
    cudaGetSymbolAddress((void**)&pool, g_pool);
    float* XCA  = pool + OFF_XCA;
    float* TMP  = pool + OFF_TMP;
    float* UP   = pool + OFF_UP;
    float* Mb   = pool + OFF_M;
    float* DWN  = pool + OFF_DWN;
    float* XB   = pool + OFF_XB;
    float* T2   = pool + OFF_T2;
    float* WBP  = pool + OFF_WBP;
    float* A1   = pool + OFF_A1;
    float* A2   = pool + OFF_A2;
    float* A3   = pool + OFF_A3;
    float* Mt   = pool + OFF_MT;
    float* XCAt = pool + OFF_XCAT;
    float* Mbt  = pool + OFF_MBT;
    float* A1t  = pool + OFF_A1T;
    float* A2t  = pool + OFF_A2T;
    float* OHt  = pool + OFF_OHT;
    float* R3t  = pool + OFF_R3T;
    float* RHt  = pool + OFF_RHT;
    float* WT   = pool + OFF_WTS;

    const int W2 = DDg * DDg;
    float* Wt_dense_ca = WT;            size_t woff = W2;
    float* Wt_ba       = WT + woff;     woff += W2;
    float* Wt_rbf3     = WT + woff;     woff += 16 * DDg;
    float* Wt_down     = WT + woff;     woff += (size_t)DDg * DTg;
    float* Wt_up_ca    = WT + woff;     woff += (size_t)DTg * DDg;
    float* Wt_up_ac    = WT + woff;     woff += (size_t)DTg * DDg;
    float* Wt_bs       = WT + woff;     woff += 2 * (size_t)W2;
    float* Wt_as       = WT + woff;     woff += 4 * (size_t)W2;
    float* Wt_au_rbf   = WT + woff;     woff += 16 * DDg;
    float* Wt_au_d1    = WT + woff;     woff += W2;
    float* Wt_au_res   = WT + woff;     woff += 6 * (size_t)W2;
    float* Wt_cat      = WT + woff;     woff += 3 * (size_t)DDg * DDg;
    float* Wt_res_m    = WT + woff;     woff += 2 * (size_t)W2;

    float* OUT_H = (float*)d_out;
    float* OUT_M = (float*)d_out + NA512;

    const float C = INV_SQRT2;

    // ---- pre-conversions ----
    run_conv(m_in, Mt, NE512);
    run_conv(rbf3, R3t, (size_t)NEg * 16);
    run_conv(rbf_h, RHt, (size_t)NEg * 16);
    run_conv(W_dense_ca, Wt_dense_ca, W2);
    run_conv(W_ba, Wt_ba, W2);
    run_conv(W_rbf3, Wt_rbf3, 16 * DDg);
    run_conv(W_down, Wt_down, (size_t)DDg * DTg);
    run_conv(W_up_ca, Wt_up_ca, (size_t)DTg * DDg);
    run_conv(W_up_ac, Wt_up_ac, (size_t)DTg * DDg);
    run_conv(W_bs, Wt_bs, 2 * (size_t)W2);
    run_conv(W_as, Wt_as, 4 * (size_t)W2);
    run_conv(W_au_rbf, Wt_au_rbf, 16 * DDg);
    run_conv(W_au_d1, Wt_au_d1, W2);
    run_conv(W_au_res, Wt_au_res, 6 * (size_t)W2);
    run_conv(W_cat, Wt_cat, 3 * (size_t)DDg * DDg);
    run_conv(W_res_m, Wt_res_m, 2 * (size_t)W2);
    permute_wbil_kernel<<<(NCBF * DTg * DTg) / 256, 256>>>(W_bil, WBP);

    // ---- pipeline ----
    run_gemm(R3t, Wt_rbf3, TMP, NEg, DDg, 16, 0);
    run_gemm(Mt, Wt_ba, TMP, NEg, DDg, DDg, F_ACT | F_MUL | F_C_TF32, nullptr, TMP);
    run_gemm(TMP, Wt_down, DWN, NEg, DTg, DDg, F_ACT | F_C_TF32);
    run_gemm(Mt, Wt_dense_ca, XCA, NEg, DDg, DDg, F_ACT);

    triplet_tmp2_kernel<<<NEg / 16, 256>>>(DWN, id3_ba, sph, rbf_w1, T2);
    run_gemm(T2, WBP, XB, NEg, DTg, NCBF * DTg, F_C_TF32);

    run_gemm(XB, Wt_up_ca, UP, NEg, DDg, DTg, F_ACT);
    run_gemm(XB, Wt_up_ac, TMP, NEg, DDg, DTg, F_ACT);
    combine_x_kernel<<<(NEg * 128) / 256, 256>>>(XCA, XCAt, UP, TMP, id_swap);

    run_gemm(XCAt, Wt_bs, TMP, NEg, DDg, DDg, F_ACT | F_C_TF32);
    run_gemm(TMP, Wt_bs + W2, Mb, NEg, DDg, DDg, F_ACT | F_ADD1 | F_ADD2 | F_OUT_TF32,
             Mbt, nullptr, XCA, C, m_in, C);

    run_gemm(Mbt, Wt_as + 0 * (size_t)W2, TMP, NEg, DDg, DDg, F_ACT | F_C_TF32);
    run_gemm(TMP, Wt_as + 1 * (size_t)W2, Mb, NEg, DDg, DDg, F_ACT | F_ADD1 | F_OUT_TF32,
             Mbt, nullptr, Mb, C);
    run_gemm(Mbt, Wt_as + 2 * (size_t)W2, TMP, NEg, DDg, DDg, F_ACT | F_C_TF32);
    run_gemm(TMP, Wt_as + 3 * (size_t)W2, Mb, NEg, DDg, DDg, F_ACT | F_ADD1 | F_OUT_TF32,
             Mbt, nullptr, Mb, C);

    run_gemm(RHt, Wt_au_rbf, UP, NEg, DDg, 16, 0);
    cudaMemsetAsync(A1, 0, NA512 * sizeof(float));
    scatter_atoms_kernel<<<(NEg * 128) / 256, 256>>>(Mb, UP, idx_t, A1);
    run_conv(A1, A1t, NA512);
    run_gemm(A1t, Wt_au_d1, A2, NAg, DDg, DDg, F_ACT | F_OUT_TF32, A2t);
    run_gemm(A2t, Wt_au_res + 0 * (size_t)W2, A3, NAg, DDg, DDg, F_ACT | F_C_TF32);
    run_gemm(A3, Wt_au_res + 1 * (size_t)W2, A2, NAg, DDg, DDg, F_ACT | F_ADD1 | F_OUT_TF32,
             A2t, nullptr, A2, C);
    run_gemm(A2t, Wt_au_res + 2 * (size_t)W2, A3, NAg, DDg, DDg, F_ACT | F_C_TF32);
    run_gemm(A3, Wt_au_res + 3 * (size_t)W2, A2, NAg, DDg, DDg, F_ACT | F_ADD1 | F_OUT_TF32,
             A2t, nullptr, A2, C);
    run_gemm(A2t, Wt_au_res + 4 * (size_t)W2, A3, NAg, DDg, DDg, F_ACT | F_C_TF32);
    run_gemm(A3, Wt_au_res + 5 * (size_t)W2, OUT_H, NAg, DDg, DDg,
             F_ACT | F_ADD1 | F_ADD2 | F_OUT_TF32, OHt, nullptr, A2, C, h_in, C);

    run_gemm(nullptr, Wt_cat, XCA, NEg, DDg, 3 * DDg, F_ACT | F_CAT | F_OUT_TF32,
             XCAt, nullptr, nullptr, 1.f, nullptr, 1.f, OHt, idx_s, idx_t, Mbt);

    run_gemm(XCAt, Wt_res_m, TMP, NEg, DDg, DDg, F_ACT | F_C_TF32);
    run_gemm(TMP, Wt_res_m + W2, OUT_M, NEg, DDg, DDg, F_ACT | F_ADD1 | F_ADD2,
             nullptr, nullptr, XCA, C, Mb, C);

    (void)in_sizes; (void)n_in; (void)out_size;
}

// round 8
// speedup vs baseline: 1.6117x; 1.6117x over previous
#include <cuda_runtime.h>
#include <cuda_fp16.h>
#include <cstdint>

// ---------------- problem constants ----------------
constexpr int NEg   = 100000;
constexpr int NAg   = 5000;
constexpr int DDg   = 512;
constexpr int DTg   = 64;
constexpr int NCBF  = 16;

constexpr float INV_SQRT2 = 0.70710678118654752f;
constexpr float ACT_SCALE = 1.0f / 0.6f;

// ---------------- scratch pool (float units; half buffers use half the floats) ----
constexpr size_t NE512  = (size_t)NEg * DDg;
constexpr size_t NE64   = (size_t)NEg * DTg;
constexpr size_t NE1024 = (size_t)NEg * 1024;
constexpr size_t NE16   = (size_t)NEg * 16;
constexpr size_t NA512  = (size_t)NAg * DDg;

constexpr size_t OFF_XCA  = 0;                       // fp32 NE512
constexpr size_t OFF_TMP  = OFF_XCA + NE512;         // fp32 NE512
constexpr size_t OFF_UP   = OFF_TMP + NE512;         // fp32 NE512
constexpr size_t OFF_MB   = OFF_UP  + NE512;         // fp32 NE512
constexpr size_t OFF_A1   = OFF_MB  + NE512;         // fp32 NA512
constexpr size_t OFF_A2   = OFF_A1  + NA512;         // fp32 NA512
// half regions (sizes given in halves; floats = halves/2)
constexpr size_t OFF_MH   = OFF_A2   + NA512;        // NE512 halves
constexpr size_t OFF_TMPH = OFF_MH   + NE512 / 2;
constexpr size_t OFF_XCAH = OFF_TMPH + NE512 / 2;
constexpr size_t OFF_MBH  = OFF_XCAH + NE512 / 2;
constexpr size_t OFF_DWNH = OFF_MBH  + NE512 / 2;    // NE64 halves
constexpr size_t OFF_XBH  = OFF_DWNH + NE64 / 2;
constexpr size_t OFF_T2H  = OFF_XBH  + NE64 / 2;     // NE1024 halves
constexpr size_t OFF_R3H  = OFF_T2H  + NE1024 / 2;   // NE16 halves
constexpr size_t OFF_RHH  = OFF_R3H  + NE16 / 2;
constexpr size_t OFF_A1H  = OFF_RHH  + NE16 / 2;     // NA512 halves
constexpr size_t OFF_A2H  = OFF_A1H  + NA512 / 2;
constexpr size_t OFF_A3H  = OFF_A2H  + NA512 / 2;
constexpr size_t OFF_OHH  = OFF_A3H  + NA512 / 2;
constexpr size_t OFF_WTSH = OFF_OHH  + NA512 / 2;    // weight halves
constexpr size_t WTSH_FLOATS = 3u * 1024 * 1024;     // 6M halves capacity
constexpr size_t POOL_TOTAL = OFF_WTSH + WTSH_FLOATS;

__device__ __align__(256) float g_pool[POOL_TOTAL];

// ---------------- helpers ----------------
__device__ __forceinline__ float scaled_silu(float x) {
    return x * (1.0f / (1.0f + __expf(-x))) * ACT_SCALE;
}
__device__ __forceinline__ void mma_f16(float4& d, const uint32_t a[4], const uint32_t b[2]) {
    asm volatile(
        "mma.sync.aligned.m16n8k16.row.col.f32.f16.f16.f32 "
        "{%0,%1,%2,%3}, {%4,%5,%6,%7}, {%8,%9}, {%0,%1,%2,%3};"
        : "+f"(d.x), "+f"(d.y), "+f"(d.z), "+f"(d.w)
        : "r"(a[0]), "r"(a[1]), "r"(a[2]), "r"(a[3]), "r"(b[0]), "r"(b[1]));
}
__device__ __forceinline__ void cp16(uint32_t smem_dst, const void* gsrc, int szbytes) {
    asm volatile("cp.async.cg.shared.global [%0], [%1], 16, %2;"
                 :: "r"(smem_dst), "l"(gsrc), "r"(szbytes));
}
__device__ __forceinline__ void cp_commit() { asm volatile("cp.async.commit_group;"); }
template <int N> __device__ __forceinline__ void cp_wait() {
    asm volatile("cp.async.wait_group %0;" :: "n"(N));
}

// ---------------- fp16 tensor-core GEMM (A [M][K] half row-major, B [N][K] half K-major) ----
enum { F_ACT = 1, F_MUL = 2, F_ADD1 = 4, F_ADD2 = 8, F_CAT = 16, F_HALF = 32, F_NOF32 = 64 };

// BK = 32 halves; smem rows padded to 40 halves (20 words) -> conflict-free frags
constexpr int SAK = 40;
constexpr int NSTAGE = 4;
constexpr int AS_BYTES = 128 * SAK * 2;               // 10240
constexpr int BS_BYTES = 128 * SAK * 2;               // 10240
constexpr int STAGE_BYTES = AS_BYTES + BS_BYTES;      // 20480
constexpr int SMEM_DYN = NSTAGE * STAGE_BYTES;        // 81920

__device__ __forceinline__ void epi2(float* C, __half* Ct, size_t idx, float vx, float vy,
                                     int flags, const float* Emul, const float* Add1, float c1,
                                     const float* Add2, float c2) {
    if (flags & F_ACT)  { vx = scaled_silu(vx);       vy = scaled_silu(vy); }
    if (flags & F_MUL)  { vx *= Emul[idx];            vy *= Emul[idx + 1]; }
    if (flags & F_ADD1) { vx = (Add1[idx] + vx) * c1; vy = (Add1[idx + 1] + vy) * c1; }
    if (flags & F_ADD2) { vx = (vx + Add2[idx]) * c2; vy = (vy + Add2[idx + 1]) * c2; }
    if (flags & F_HALF) *(__half2*)(Ct + idx) = __floats2half2_rn(vx, vy);
    if (!(flags & F_NOF32)) { C[idx] = vx; C[idx + 1] = vy; }
}

__global__ __launch_bounds__(256, 2)
void mma_gemm_kernel(const __half* __restrict__ A, const __half* __restrict__ Bt,
                     float* __restrict__ C, __half* __restrict__ Ct,
                     int M, int N, int K, int flags,
                     const float* __restrict__ Emul,
                     const float* __restrict__ Add1, float c1,
                     const float* __restrict__ Add2, float c2,
                     const __half* __restrict__ Hg, const int* __restrict__ idxs,
                     const int* __restrict__ idxt, const __half* __restrict__ Mg)
{
    extern __shared__ __align__(16) char dyn_smem[];

    const int t = threadIdx.x;            // 256 threads
    const int lane = t & 31;
    const int warp = t >> 5;
    const int wm = (warp >> 2) * 64;      // 2 warps in M
    const int wn = (warp & 3) * 32;       // 4 warps in N
    const int rowC0 = blockIdx.y * 128;
    const int colC0 = blockIdx.x * 128;

    const uint32_t smem0 = (uint32_t)__cvta_generic_to_shared(dyn_smem);

    // A loads: thread t -> row t&127, k-off (t>>7)*16 halves; 2 chunks of 8 halves
    const int arow_l = t & 127;
    const int ako = (t >> 7) * 16;
    const int arow = rowC0 + arow_l;
    const bool aok = arow < M;
    int isg = 0, itg = 0;
    if ((flags & F_CAT) && aok) { isg = idxs[arow]; itg = idxt[arow]; }
    const uint32_t a_dst = smem0 + (uint32_t)(arow_l * SAK + ako) * 2;

    // B loads: thread t -> n-row t&127 of Bt, k-off (t>>7)*16
    const int brow_l = t & 127;
    const bool bok = (colC0 + brow_l) < N;
    const __half* brp = Bt + (size_t)(bok ? (colC0 + brow_l) : 0) * K;
    const uint32_t b_dst = smem0 + AS_BYTES + (uint32_t)(brow_l * SAK + ako) * 2;

    float4 acc[4][4];
#pragma unroll
    for (int i = 0; i < 4; i++)
#pragma unroll
        for (int j = 0; j < 4; j++) acc[i][j] = make_float4(0.f, 0.f, 0.f, 0.f);

    auto loadTile = [&](int s, int k0) {
        const uint32_t soff = (uint32_t)s * STAGE_BYTES;
        // ---- A ----
        const __half* ap;
        if (!(flags & F_CAT)) {
            ap = A + (size_t)(aok ? arow : 0) * K + k0 + ako;
        } else {
            const int k = k0 + ako;
            if (k < 512)       ap = Hg + (size_t)isg * 512 + k;
            else if (k < 1024) ap = Hg + (size_t)itg * 512 + (k - 512);
            else               ap = Mg + (size_t)(aok ? arow : 0) * 512 + (k - 1024);
        }
#pragma unroll
        for (int ch = 0; ch < 2; ch++) {
            const bool ok = aok && (k0 + ako + ch * 8) < K;
            cp16(a_dst + soff + 16u * ch, ok ? (const void*)(ap + 8 * ch) : (const void*)A,
                 ok ? 16 : 0);
        }
        // ---- B ----
        const __half* bp = brp + k0 + ako;
#pragma unroll
        for (int ch = 0; ch < 2; ch++) {
            const bool ok = bok && (k0 + ako + ch * 8) < K;
            cp16(b_dst + soff + 16u * ch, ok ? (const void*)(bp + 8 * ch) : (const void*)Bt,
                 ok ? 16 : 0);
        }
    };

    auto computeTile = [&](int s) {
        const uint32_t* Au = (const uint32_t*)(dyn_smem + (size_t)s * STAGE_BYTES);
        const uint32_t* Bu = (const uint32_t*)(dyn_smem + (size_t)s * STAGE_BYTES + AS_BYTES);
        const int c = lane & 3;
        const int rbase = wm + (lane >> 2);
        const int nbase = wn + (lane >> 2);
#pragma unroll
        for (int g = 0; g < 2; g++) {       // two k16 groups within BK=32
            uint32_t af[4][4];
            uint32_t bf[4][2];
#pragma unroll
            for (int mt = 0; mt < 4; mt++) {
                const int r = rbase + mt * 16;
                af[mt][0] = Au[r * 20 + g * 8 + c];
                af[mt][1] = Au[(r + 8) * 20 + g * 8 + c];
                af[mt][2] = Au[r * 20 + g * 8 + 4 + c];
                af[mt][3] = Au[(r + 8) * 20 + g * 8 + 4 + c];
            }
#pragma unroll
            for (int nt = 0; nt < 4; nt++) {
                const int n = nbase + nt * 8;
                bf[nt][0] = Bu[n * 20 + g * 8 + c];
                bf[nt][1] = Bu[n * 20 + g * 8 + 4 + c];
            }
#pragma unroll
            for (int mt = 0; mt < 4; mt++)
#pragma unroll
                for (int nt = 0; nt < 4; nt++)
                    mma_f16(acc[mt][nt], af[mt], bf[nt]);
        }
    };

    const int nK = (K + 31) >> 5;
    const int pre = nK < (NSTAGE - 1) ? nK : (NSTAGE - 1);
    for (int s = 0; s < pre; s++) { loadTile(s, s * 32); cp_commit(); }

    for (int i = 0; i < nK; ++i) {
        const int rem = nK - 1 - i;
        if (rem >= 2)      cp_wait<2>();
        else if (rem == 1) cp_wait<1>();
        else               cp_wait<0>();
        __syncthreads();
        // refilled stage (i-1)&3 has no pending consumers after the sync above
        if (i + NSTAGE - 1 < nK) { loadTile((i + NSTAGE - 1) & 3, (i + NSTAGE - 1) * 32); cp_commit(); }
        computeTile(i & 3);
    }

    // epilogue (warp tile 64x32)
#pragma unroll
    for (int mt = 0; mt < 4; mt++) {
        const int r = rowC0 + wm + mt * 16 + (lane >> 2);
#pragma unroll
        for (int nt = 0; nt < 4; nt++) {
            const int cc = colC0 + wn + nt * 8 + (lane & 3) * 2;
            if (cc >= N) continue;
            const float4 v = acc[mt][nt];
            if (r < M)
                epi2(C, Ct, (size_t)r * N + cc, v.x, v.y, flags, Emul, Add1, c1, Add2, c2);
            if (r + 8 < M)
                epi2(C, Ct, (size_t)(r + 8) * N + cc, v.z, v.w, flags, Emul, Add1, c1, Add2, c2);
        }
    }
}

// ---------------- fp32 -> fp16 conversion ----------------
__global__ void conv_half_kernel(const float* __restrict__ src, __half* __restrict__ dst, int n4) {
    const int i = blockIdx.x * blockDim.x + threadIdx.x;
    if (i >= n4) return;
    float4 v = ((const float4*)src)[i];
    __half2* d = (__half2*)dst + 2 * i;
    d[0] = __floats2half2_rn(v.x, v.y);
    d[1] = __floats2half2_rn(v.z, v.w);
}

// ---------------- weight transpose -> half: dst[n][k] = half(src[k][n]) ----------------
__global__ void transpose_half_kernel(const float* __restrict__ src, __half* __restrict__ dst,
                                      int K, int N) {
    __shared__ float tile[32][33];
    const int kb = blockIdx.y * 32, nb = blockIdx.x * 32;
    const int tx = threadIdx.x, ty = threadIdx.y;
#pragma unroll
    for (int dy = 0; dy < 32; dy += 8) {
        const int k = kb + ty + dy, n = nb + tx;
        if (k < K && n < N) tile[ty + dy][tx] = src[(size_t)k * N + n];
    }
    __syncthreads();
#pragma unroll
    for (int dy = 0; dy < 32; dy += 8) {
        const int n = nb + ty + dy, k = kb + tx;
        if (n < N && k < K) dst[(size_t)n * K + k] = __float2half_rn(tile[tx][ty + dy]);
    }
}

// ---------------- triplet tmp2 (half in, half out) ----------------
__global__ void triplet_tmp2_kernel(const __half* __restrict__ down,
                                    const int* __restrict__ id3_ba,
                                    const float* __restrict__ sph,
                                    const float* __restrict__ rbfw1,
                                    __half* __restrict__ t2)
{
    __shared__ int   sIdx[256];
    __shared__ float sS[16 * 112];
    __shared__ float sR[16 * 112];

    const int tid = threadIdx.x;
    const int e0 = blockIdx.x * 16;

    sIdx[tid] = id3_ba[(size_t)e0 * 16 + tid];
    for (int r = tid; r < 16 * 112; r += 256) {
        sS[r] = sph  [(size_t)e0 * 112 + r];
        sR[r] = rbfw1[(size_t)e0 * 112 + r];
    }
    __syncthreads();

    const int team = tid >> 4;
    const int j = tid & 15;
    const int edge = e0 + team;

    float4 G[16];
#pragma unroll
    for (int k = 0; k < 16; k++) {
        const int row = sIdx[team * 16 + k];
        const __half2* dp = (const __half2*)(down + (size_t)row * 64 + j * 4);
        float2 lo = __half22float2(dp[0]);
        float2 hi = __half22float2(dp[1]);
        G[k] = make_float4(lo.x, lo.y, hi.x, hi.y);
    }

    float4 t1[7];
#pragma unroll
    for (int s = 0; s < 7; s++) {
        float4 a = make_float4(0.f, 0.f, 0.f, 0.f);
#pragma unroll
        for (int k = 0; k < 16; k++) {
            const float f = sS[team * 112 + s * 16 + k];
            a.x = fmaf(f, G[k].x, a.x); a.y = fmaf(f, G[k].y, a.y);
            a.z = fmaf(f, G[k].z, a.z); a.w = fmaf(f, G[k].w, a.w);
        }
        t1[s] = a;
    }

#pragma unroll
    for (int i = 0; i < 16; i++) {
        float4 a = make_float4(0.f, 0.f, 0.f, 0.f);
#pragma unroll
        for (int s = 0; s < 7; s++) {
            const float f = sR[team * 112 + i * 7 + s];
            a.x = fmaf(f, t1[s].x, a.x); a.y = fmaf(f, t1[s].y, a.y);
            a.z = fmaf(f, t1[s].z, a.z); a.w = fmaf(f, t1[s].w, a.w);
        }
        __half2* out = (__half2*)(t2 + (size_t)edge * 1024 + i * 64 + j * 4);
        out[0] = __floats2half2_rn(a.x, a.y);
        out[1] = __floats2half2_rn(a.z, a.w);
    }
}

// W_bil[e,i,o] -> WBPh[o][i*64+e]  ([64][1024] half, K-major)
__global__ void permute_wbil_kernel(const float* __restrict__ wb, __half* __restrict__ out) {
    const int idx = blockIdx.x * blockDim.x + threadIdx.x;
    const int o = idx & 63;
    const int i = (idx >> 6) & 15;
    const int e = idx >> 10;
    out[(size_t)o * 1024 + i * 64 + e] = __float2half_rn(wb[((size_t)(e * 16 + i)) * 64 + o]);
}

// x = (xca_skip + (up + ac[id_swap])*c)*c  -> fp32 XCA + half XCAh
__global__ void combine_x_kernel(float* xca, __half* xcah, const float* __restrict__ up,
                                 const float* __restrict__ ac, const int* __restrict__ id_swap) {
    const int idx = blockIdx.x * blockDim.x + threadIdx.x;
    const int e = idx >> 7;
    const int c = idx & 127;
    const int es = id_swap[e];
    float4 a = ((const float4*)up)[idx];
    float4 b = ((const float4*)ac)[(size_t)es * 128 + c];
    float4 x = ((float4*)xca)[idx];
    x.x = (x.x + (a.x + b.x) * INV_SQRT2) * INV_SQRT2;
    x.y = (x.y + (a.y + b.y) * INV_SQRT2) * INV_SQRT2;
    x.z = (x.z + (a.z + b.z) * INV_SQRT2) * INV_SQRT2;
    x.w = (x.w + (a.w + b.w) * INV_SQRT2) * INV_SQRT2;
    ((float4*)xca)[idx] = x;
    __half2* xh = (__half2*)xcah + 2 * idx;
    xh[0] = __floats2half2_rn(x.x, x.y);
    xh[1] = __floats2half2_rn(x.z, x.w);
}

// segment-sum: out[idx_t[e]] += m[e]*r2[e]
__global__ void scatter_atoms_kernel(const float* __restrict__ m, const float* __restrict__ r2,
                                     const int* __restrict__ idx_t, float* out) {
    const int idx = blockIdx.x * blockDim.x + threadIdx.x;
    const int e = idx >> 7;
    const int c = idx & 127;
    const int t = idx_t[e];
    float4 a = ((const float4*)m)[idx];
    float4 b = ((const float4*)r2)[idx];
    float* dst = out + (size_t)t * 512 + c * 4;
    atomicAdd(dst + 0, a.x * b.x);
    atomicAdd(dst + 1, a.y * b.y);
    atomicAdd(dst + 2, a.z * b.z);
    atomicAdd(dst + 3, a.w * b.w);
}

// ---------------- host orchestration ----------------
static void run_gemm(const __half* A, const __half* Bt, float* C, int M, int N, int K, int flags,
                     __half* Ct = nullptr,
                     const float* E = nullptr,
                     const float* Ad1 = nullptr, float c1 = 1.f,
                     const float* Ad2 = nullptr, float c2 = 1.f,
                     const __half* Hg = nullptr, const int* isx = nullptr,
                     const int* itx = nullptr, const __half* Mg = nullptr)
{
    static bool attr_set = false;
    if (!attr_set) {
        cudaFuncSetAttribute(mma_gemm_kernel, cudaFuncAttributeMaxDynamicSharedMemorySize, SMEM_DYN);
        attr_set = true;
    }
    dim3 grid((N + 127) / 128, (M + 127) / 128);
    mma_gemm_kernel<<<grid, 256, SMEM_DYN>>>(A, Bt, C, Ct, M, N, K, flags,
                                             E, Ad1, c1, Ad2, c2, Hg, isx, itx, Mg);
}
static void run_conv(const float* src, __half* dst, size_t n) {
    const int n4 = (int)(n / 4);
    conv_half_kernel<<<(n4 + 255) / 256, 256>>>(src, dst, n4);
}
static void run_transpose(const float* src, __half* dst, int K, int N) {
    dim3 grid((N + 31) / 32, (K + 31) / 32);
    transpose_half_kernel<<<grid, dim3(32, 8)>>>(src, dst, K, N);
}

extern "C" void kernel_launch(void* const* d_in, const int* in_sizes, int n_in,
                              void* d_out, int out_size)
{
    const float* h_in    = (const float*)d_in[0];
    const float* m_in    = (const float*)d_in[1];
    const float* rbf3    = (const float*)d_in[2];
    const float* rbf_w1  = (const float*)d_in[3];
    const float* sph     = (const float*)d_in[4];
    const float* rbf_h   = (const float*)d_in[5];
    const int*   id3_ba  = (const int*)d_in[6];
    const int*   id_swap = (const int*)d_in[9];
    const int*   idx_s   = (const int*)d_in[10];
    const int*   idx_t   = (const int*)d_in[11];
    const float* W_dense_ca = (const float*)d_in[12];
    const float* W_ba    = (const float*)d_in[13];
    const float* W_rbf3  = (const float*)d_in[14];
    const float* W_down  = (const float*)d_in[15];
    const float* W_bil   = (const float*)d_in[16];
    const float* W_up_ca = (const float*)d_in[17];
    const float* W_up_ac = (const float*)d_in[18];
    const float* W_bs    = (const float*)d_in[19];
    const float* W_as    = (const float*)d_in[20];
    const float* W_au_rbf= (const float*)d_in[21];
    const float* W_au_d1 = (const float*)d_in[22];
    const float* W_au_res= (const float*)d_in[23];
    const float* W_cat   = (const float*)d_in[24];
    const float* W_res_m = (const float*)d_in[25];

    float* pool = nullptr;
    cudaGetSymbolAddress((void**)&pool, g_pool);
    float*  XCA  = pool + OFF_XCA;
    float*  TMP  = pool + OFF_TMP;
    float*  UP   = pool + OFF_UP;
    float*  Mb   = pool + OFF_MB;
    float*  A1   = pool + OFF_A1;
    float*  A2   = pool + OFF_A2;
    __half* Mh   = (__half*)(pool + OFF_MH);
    __half* TMPh = (__half*)(pool + OFF_TMPH);
    __half* XCAh = (__half*)(pool + OFF_XCAH);
    __half* Mbh  = (__half*)(pool + OFF_MBH);
    __half* DWNh = (__half*)(pool + OFF_DWNH);
    __half* XBh  = (__half*)(pool + OFF_XBH);
    __half* T2h  = (__half*)(pool + OFF_T2H);
    __half* R3h  = (__half*)(pool + OFF_R3H);
    __half* RHh  = (__half*)(pool + OFF_RHH);
    __half* A1h  = (__half*)(pool + OFF_A1H);
    __half* A2h  = (__half*)(pool + OFF_A2H);
    __half* A3h  = (__half*)(pool + OFF_A3H);
    __half* OHh  = (__half*)(pool + OFF_OHH);
    __half* WH   = (__half*)(pool + OFF_WTSH);

    const size_t W2 = (size_t)DDg * DDg;
    // transposed half weights [N][K]
    __half* Wh_dense_ca = WH;            size_t woff = W2;
    __half* Wh_ba       = WH + woff;     woff += W2;
    __half* Wh_rbf3     = WH + woff;     woff += (size_t)DDg * 16;
    __half* Wh_down     = WH + woff;     woff += (size_t)DTg * DDg;
    __half* Wh_up_ca    = WH + woff;     woff += (size_t)DDg * DTg;
    __half* Wh_up_ac    = WH + woff;     woff += (size_t)DDg * DTg;
    __half* Wh_bs       = WH + woff;     woff += 2 * W2;
    __half* Wh_as       = WH + woff;     woff += 4 * W2;
    __half* Wh_au_rbf   = WH + woff;     woff += (size_t)DDg * 16;
    __half* Wh_au_d1    = WH + woff;     woff += W2;
    __half* Wh_au_res   = WH + woff;     woff += 6 * W2;
    __half* Wh_cat      = WH + woff;     woff += 3 * W2;
    __half* Wh_res_m    = WH + woff;     woff += 2 * W2;
    __half* WBPh        = WH + woff;     woff += (size_t)DTg * 1024;

    float* OUT_H = (float*)d_out;
    float* OUT_M = (float*)d_out + NA512;

    const float C = INV_SQRT2;

    // ---- pre-conversions ----
    run_conv(m_in, Mh, NE512);
    run_conv(rbf3, R3h, NE16);
    run_conv(rbf_h, RHh, NE16);
    run_transpose(W_dense_ca, Wh_dense_ca, DDg, DDg);
    run_transpose(W_ba, Wh_ba, DDg, DDg);
    run_transpose(W_rbf3, Wh_rbf3, 16, DDg);
    run_transpose(W_down, Wh_down, DDg, DTg);
    run_transpose(W_up_ca, Wh_up_ca, DTg, DDg);
    run_transpose(W_up_ac, Wh_up_ac, DTg, DDg);
    for (int i = 0; i < 2; i++) run_transpose(W_bs + i * W2, Wh_bs + i * W2, DDg, DDg);
    for (int i = 0; i < 4; i++) run_transpose(W_as + i * W2, Wh_as + i * W2, DDg, DDg);
    run_transpose(W_au_rbf, Wh_au_rbf, 16, DDg);
    run_transpose(W_au_d1, Wh_au_d1, DDg, DDg);
    for (int i = 0; i < 6; i++) run_transpose(W_au_res + i * W2, Wh_au_res + i * W2, DDg, DDg);
    run_transpose(W_cat, Wh_cat, 3 * DDg, DDg);
    for (int i = 0; i < 2; i++) run_transpose(W_res_m + i * W2, Wh_res_m + i * W2, DDg, DDg);
    permute_wbil_kernel<<<(NCBF * DTg * DTg) / 256, 256>>>(W_bil, WBPh);

    // ---- pipeline ----
    // TMP = rbf3 @ W_rbf3 (fp32, Emul later)
    run_gemm(R3h, Wh_rbf3, TMP, NEg, DDg, 16, 0);
    // TMPh = half(act(m @ W_ba) * TMP)
    run_gemm(Mh, Wh_ba, nullptr, NEg, DDg, DDg, F_ACT | F_MUL | F_HALF | F_NOF32,
             TMPh, TMP);
    // DWNh = half(act(TMPh @ W_down))
    run_gemm(TMPh, Wh_down, nullptr, NEg, DTg, DDg, F_ACT | F_HALF | F_NOF32, DWNh);
    // XCA = act(m @ W_dense_ca) (fp32 skip)
    run_gemm(Mh, Wh_dense_ca, XCA, NEg, DDg, DDg, F_ACT);

    triplet_tmp2_kernel<<<NEg / 16, 256>>>(DWNh, id3_ba, sph, rbf_w1, T2h);
    // XBh = half(T2h @ WBPh)
    run_gemm(T2h, WBPh, nullptr, NEg, DTg, NCBF * DTg, F_HALF | F_NOF32, XBh);

    run_gemm(XBh, Wh_up_ca, UP, NEg, DDg, DTg, F_ACT);
    run_gemm(XBh, Wh_up_ac, TMP, NEg, DDg, DTg, F_ACT);
    combine_x_kernel<<<(NEg * 128) / 256, 256>>>(XCA, XCAh, UP, TMP, id_swap);

    // W_bs residual, fused with m = (m + x)*c
    run_gemm(XCAh, Wh_bs, nullptr, NEg, DDg, DDg, F_ACT | F_HALF | F_NOF32, TMPh);
    run_gemm(TMPh, Wh_bs + W2, Mb, NEg, DDg, DDg, F_ACT | F_ADD1 | F_ADD2 | F_HALF,
             Mbh, nullptr, XCA, C, m_in, C);

    // W_as residuals (2)
    run_gemm(Mbh, Wh_as + 0 * W2, nullptr, NEg, DDg, DDg, F_ACT | F_HALF | F_NOF32, TMPh);
    run_gemm(TMPh, Wh_as + 1 * W2, Mb, NEg, DDg, DDg, F_ACT | F_ADD1 | F_HALF,
             Mbh, nullptr, Mb, C);
    run_gemm(Mbh, Wh_as + 2 * W2, nullptr, NEg, DDg, DDg, F_ACT | F_HALF | F_NOF32, TMPh);
    run_gemm(TMPh, Wh_as + 3 * W2, Mb, NEg, DDg, DDg, F_ACT | F_ADD1 | F_HALF,
             Mbh, nullptr, Mb, C);

    // AtomUpdate
    run_gemm(RHh, Wh_au_rbf, UP, NEg, DDg, 16, 0);
    cudaMemsetAsync(A1, 0, NA512 * sizeof(float));
    scatter_atoms_kernel<<<(NEg * 128) / 256, 256>>>(Mb, UP, idx_t, A1);
    run_conv(A1, A1h, NA512);
    run_gemm(A1h, Wh_au_d1, A2, NAg, DDg, DDg, F_ACT | F_HALF, A2h);
    run_gemm(A2h, Wh_au_res + 0 * W2, nullptr, NAg, DDg, DDg, F_ACT | F_HALF | F_NOF32, A3h);
    run_gemm(A3h, Wh_au_res + 1 * W2, A2, NAg, DDg, DDg, F_ACT | F_ADD1 | F_HALF,
             A2h, nullptr, A2, C);
    run_gemm(A2h, Wh_au_res + 2 * W2, nullptr, NAg, DDg, DDg, F_ACT | F_HALF | F_NOF32, A3h);
    run_gemm(A3h, Wh_au_res + 3 * W2, A2, NAg, DDg, DDg, F_ACT | F_ADD1 | F_HALF,
             A2h, nullptr, A2, C);
    run_gemm(A2h, Wh_au_res + 4 * W2, nullptr, NAg, DDg, DDg, F_ACT | F_HALF | F_NOF32, A3h);
    run_gemm(A3h, Wh_au_res + 5 * W2, OUT_H, NAg, DDg, DDg,
             F_ACT | F_ADD1 | F_ADD2 | F_HALF, OHh, nullptr, A2, C, h_in, C);

    // EdgeEmbedding (fused gather concat GEMM)
    run_gemm(nullptr, Wh_cat, XCA, NEg, DDg, 3 * DDg, F_ACT | F_CAT | F_HALF,
             XCAh, nullptr, nullptr, 1.f, nullptr, 1.f, OHh, idx_s, idx_t, Mbh);

    // W_res_m residual, fused with m_out = (m + mc)*c
    run_gemm(XCAh, Wh_res_m, nullptr, NEg, DDg, DDg, F_ACT | F_HALF | F_NOF32, TMPh);
    run_gemm(TMPh, Wh_res_m + W2, OUT_M, NEg, DDg, DDg, F_ACT | F_ADD1 | F_ADD2,
             nullptr, nullptr, XCA, C, Mb, C);

    (void)in_sizes; (void)n_in; (void)out_size;
}

// round 9
// speedup vs baseline: 1.6980x; 1.0535x over previous
#include <cuda_runtime.h>
#include <cuda_fp16.h>
#include <cstdint>

// ---------------- problem constants ----------------
constexpr int NEg   = 100000;
constexpr int NAg   = 5000;
constexpr int DDg   = 512;
constexpr int DTg   = 64;
constexpr int NCBF  = 16;

constexpr float INV_SQRT2 = 0.70710678118654752f;
constexpr float ACT_SCALE = 1.0f / 0.6f;

// ---------------- scratch pool (float units; half buffers use half the floats) ----
constexpr size_t NE512  = (size_t)NEg * DDg;
constexpr size_t NE64   = (size_t)NEg * DTg;
constexpr size_t NE1024 = (size_t)NEg * 1024;
constexpr size_t NE16   = (size_t)NEg * 16;
constexpr size_t NA512  = (size_t)NAg * DDg;

constexpr size_t OFF_XCA  = 0;                       // fp32 NE512
constexpr size_t OFF_TMP  = OFF_XCA + NE512;         // fp32 NE512
constexpr size_t OFF_UP   = OFF_TMP + NE512;         // fp32 NE512
constexpr size_t OFF_MB   = OFF_UP  + NE512;         // fp32 NE512
constexpr size_t OFF_A1   = OFF_MB  + NE512;         // fp32 NA512
constexpr size_t OFF_A2   = OFF_A1  + NA512;         // fp32 NA512
// half regions
constexpr size_t OFF_MH   = OFF_A2   + NA512;        // NE512 halves
constexpr size_t OFF_TMPH = OFF_MH   + NE512 / 2;
constexpr size_t OFF_XCAH = OFF_TMPH + NE512 / 2;
constexpr size_t OFF_MBH  = OFF_XCAH + NE512 / 2;
constexpr size_t OFF_DWNH = OFF_MBH  + NE512 / 2;    // NE64 halves
constexpr size_t OFF_XBH  = OFF_DWNH + NE64 / 2;
constexpr size_t OFF_T2H  = OFF_XBH  + NE64 / 2;     // NE1024 halves
constexpr size_t OFF_R3H  = OFF_T2H  + NE1024 / 2;   // NE16 halves
constexpr size_t OFF_RHH  = OFF_R3H  + NE16 / 2;
constexpr size_t OFF_A1H  = OFF_RHH  + NE16 / 2;     // NA512 halves
constexpr size_t OFF_A2H  = OFF_A1H  + NA512 / 2;
constexpr size_t OFF_A3H  = OFF_A2H  + NA512 / 2;
constexpr size_t OFF_OHH  = OFF_A3H  + NA512 / 2;
constexpr size_t OFF_WTSH = OFF_OHH  + NA512 / 2;    // weight halves
constexpr size_t WTSH_FLOATS = 3u * 1024 * 1024;
constexpr size_t POOL_TOTAL = OFF_WTSH + WTSH_FLOATS;

__device__ __align__(256) float g_pool[POOL_TOTAL];

// ---------------- helpers ----------------
__device__ __forceinline__ float scaled_silu(float x) {
    return x * (1.0f / (1.0f + __expf(-x))) * ACT_SCALE;
}
__device__ __forceinline__ void mma_f16(float4& d, const uint32_t a[4], const uint32_t b[2]) {
    asm volatile(
        "mma.sync.aligned.m16n8k16.row.col.f32.f16.f16.f32 "
        "{%0,%1,%2,%3}, {%4,%5,%6,%7}, {%8,%9}, {%0,%1,%2,%3};"
        : "+f"(d.x), "+f"(d.y), "+f"(d.z), "+f"(d.w)
        : "r"(a[0]), "r"(a[1]), "r"(a[2]), "r"(a[3]), "r"(b[0]), "r"(b[1]));
}
__device__ __forceinline__ void ldsm_x4(uint32_t& r0, uint32_t& r1, uint32_t& r2, uint32_t& r3,
                                        uint32_t addr) {
    asm volatile("ldmatrix.sync.aligned.m8n8.x4.shared.b16 {%0,%1,%2,%3}, [%4];"
                 : "=r"(r0), "=r"(r1), "=r"(r2), "=r"(r3) : "r"(addr));
}
__device__ __forceinline__ void cp16(uint32_t smem_dst, const void* gsrc, int szbytes) {
    asm volatile("cp.async.cg.shared.global [%0], [%1], 16, %2;"
                 :: "r"(smem_dst), "l"(gsrc), "r"(szbytes));
}
__device__ __forceinline__ void cp_commit() { asm volatile("cp.async.commit_group;"); }
template <int N> __device__ __forceinline__ void cp_wait() {
    asm volatile("cp.async.wait_group %0;" :: "n"(N));
}

// ---------------- fp16 tensor-core GEMM (A [M][K] half row-major, B [N][K] half K-major) ----
enum { F_ACT = 1, F_MUL = 2, F_ADD1 = 4, F_ADD2 = 8, F_CAT = 16, F_HALF = 32, F_NOF32 = 64 };

// BK = 32 halves; smem rows padded to 40 halves -> conflict-free ldmatrix
constexpr int SAK = 40;
constexpr int NSTAGE = 4;
constexpr int AS_BYTES = 128 * SAK * 2;               // 10240
constexpr int STAGE_BYTES = 2 * AS_BYTES;             // 20480
constexpr int SMEM_DYN = NSTAGE * STAGE_BYTES;        // 81920

__device__ __forceinline__ void epi2(float* C, __half* Ct, size_t idx, float vx, float vy,
                                     int flags, const float* Emul, const float* Add1, float c1,
                                     const float* Add2, float c2) {
    if (flags & F_ACT)  { vx = scaled_silu(vx);       vy = scaled_silu(vy); }
    if (flags & F_MUL)  { vx *= Emul[idx];            vy *= Emul[idx + 1]; }
    if (flags & F_ADD1) { vx = (Add1[idx] + vx) * c1; vy = (Add1[idx + 1] + vy) * c1; }
    if (flags & F_ADD2) { vx = (vx + Add2[idx]) * c2; vy = (vy + Add2[idx + 1]) * c2; }
    if (flags & F_HALF) *(__half2*)(Ct + idx) = __floats2half2_rn(vx, vy);
    if (!(flags & F_NOF32)) { C[idx] = vx; C[idx + 1] = vy; }
}

__global__ __launch_bounds__(256, 2)
void mma_gemm_kernel(const __half* __restrict__ A, const __half* __restrict__ Bt,
                     float* __restrict__ C, __half* __restrict__ Ct,
                     int M, int N, int K, int flags,
                     const float* __restrict__ Emul,
                     const float* __restrict__ Add1, float c1,
                     const float* __restrict__ Add2, float c2,
                     const __half* __restrict__ Hg, const int* __restrict__ idxs,
                     const int* __restrict__ idxt, const __half* __restrict__ Mg)
{
    extern __shared__ __align__(16) char dyn_smem[];

    const int t = threadIdx.x;            // 256 threads
    const int lane = t & 31;
    const int warp = t >> 5;
    const int wm = (warp >> 2) * 64;      // 2 warps in M
    const int wn = (warp & 3) * 32;       // 4 warps in N
    const int rowC0 = blockIdx.y * 128;
    const int colC0 = blockIdx.x * 128;

    const uint32_t smem0 = (uint32_t)__cvta_generic_to_shared(dyn_smem);

    // A loads: thread t -> row t&127, k-off (t>>7)*16 halves; 2 chunks of 8 halves
    const int arow_l = t & 127;
    const int ako = (t >> 7) * 16;
    const int arow = rowC0 + arow_l;
    const bool aok = arow < M;
    int isg = 0, itg = 0;
    if ((flags & F_CAT) && aok) { isg = idxs[arow]; itg = idxt[arow]; }
    const uint32_t a_dst = smem0 + (uint32_t)(arow_l * SAK + ako) * 2;

    // B loads: thread t -> n-row t&127 of Bt, k-off (t>>7)*16
    const int brow_l = t & 127;
    const bool bok = (colC0 + brow_l) < N;
    const __half* brp = Bt + (size_t)(bok ? (colC0 + brow_l) : 0) * K;
    const uint32_t b_dst = smem0 + AS_BYTES + (uint32_t)(brow_l * SAK + ako) * 2;

    // ldmatrix per-lane address components
    const int a_row_lm = wm + (lane & 15);                 // + mt*16
    const int a_kh_lm  = (lane >> 4) * 8;                  // + g*16
    const int b_row_lm = wn + (lane & 7) + (lane >> 4) * 8; // + p*16
    const int b_kh_lm  = ((lane >> 3) & 1) * 8;            // + g*16

    float4 acc[4][4];
#pragma unroll
    for (int i = 0; i < 4; i++)
#pragma unroll
        for (int j = 0; j < 4; j++) acc[i][j] = make_float4(0.f, 0.f, 0.f, 0.f);

    auto loadTile = [&](int s, int k0) {
        const uint32_t soff = (uint32_t)s * STAGE_BYTES;
        const __half* ap;
        if (!(flags & F_CAT)) {
            ap = A + (size_t)(aok ? arow : 0) * K + k0 + ako;
        } else {
            const int k = k0 + ako;
            if (k < 512)       ap = Hg + (size_t)isg * 512 + k;
            else if (k < 1024) ap = Hg + (size_t)itg * 512 + (k - 512);
            else               ap = Mg + (size_t)(aok ? arow : 0) * 512 + (k - 1024);
        }
#pragma unroll
        for (int ch = 0; ch < 2; ch++) {
            const bool ok = aok && (k0 + ako + ch * 8) < K;
            cp16(a_dst + soff + 16u * ch, ok ? (const void*)(ap + 8 * ch) : (const void*)A,
                 ok ? 16 : 0);
        }
        const __half* bp = brp + k0 + ako;
#pragma unroll
        for (int ch = 0; ch < 2; ch++) {
            const bool ok = bok && (k0 + ako + ch * 8) < K;
            cp16(b_dst + soff + 16u * ch, ok ? (const void*)(bp + 8 * ch) : (const void*)Bt,
                 ok ? 16 : 0);
        }
    };

    auto computeTile = [&](int s) {
        const uint32_t abase = smem0 + (uint32_t)s * STAGE_BYTES;
        const uint32_t bbase = abase + AS_BYTES;
#pragma unroll
        for (int g = 0; g < 2; g++) {       // two k16 groups within BK=32
            uint32_t af[4][4];
            uint32_t bf[4][2];
#pragma unroll
            for (int mt = 0; mt < 4; mt++)
                ldsm_x4(af[mt][0], af[mt][1], af[mt][2], af[mt][3],
                        abase + (uint32_t)((a_row_lm + mt * 16) * SAK + g * 16 + a_kh_lm) * 2);
#pragma unroll
            for (int p = 0; p < 2; p++)
                ldsm_x4(bf[2 * p][0], bf[2 * p][1], bf[2 * p + 1][0], bf[2 * p + 1][1],
                        bbase + (uint32_t)((b_row_lm + p * 16) * SAK + g * 16 + b_kh_lm) * 2);
#pragma unroll
            for (int mt = 0; mt < 4; mt++)
#pragma unroll
                for (int nt = 0; nt < 4; nt++)
                    mma_f16(acc[mt][nt], af[mt], bf[nt]);
        }
    };

    const int nK = (K + 31) >> 5;
    const int pre = nK < (NSTAGE - 1) ? nK : (NSTAGE - 1);
    for (int s = 0; s < pre; s++) { loadTile(s, s * 32); cp_commit(); }

    for (int i = 0; i < nK; ++i) {
        const int rem = nK - 1 - i;
        if (rem >= 2)      cp_wait<2>();
        else if (rem == 1) cp_wait<1>();
        else               cp_wait<0>();
        __syncthreads();
        if (i + NSTAGE - 1 < nK) { loadTile((i + NSTAGE - 1) & 3, (i + NSTAGE - 1) * 32); cp_commit(); }
        computeTile(i & 3);
    }

    // epilogue (warp tile 64x32)
#pragma unroll
    for (int mt = 0; mt < 4; mt++) {
        const int r = rowC0 + wm + mt * 16 + (lane >> 2);
#pragma unroll
        for (int nt = 0; nt < 4; nt++) {
            const int cc = colC0 + wn + nt * 8 + (lane & 3) * 2;
            if (cc >= N) continue;
            const float4 v = acc[mt][nt];
            if (r < M)
                epi2(C, Ct, (size_t)r * N + cc, v.x, v.y, flags, Emul, Add1, c1, Add2, c2);
            if (r + 8 < M)
                epi2(C, Ct, (size_t)(r + 8) * N + cc, v.z, v.w, flags, Emul, Add1, c1, Add2, c2);
        }
    }
}

// ---------------- fp32 -> fp16 conversion ----------------
__global__ void conv_half_kernel(const float* __restrict__ src, __half* __restrict__ dst, int n4) {
    const int i = blockIdx.x * blockDim.x + threadIdx.x;
    if (i >= n4) return;
    float4 v = ((const float4*)src)[i];
    __half2* d = (__half2*)dst + 2 * i;
    d[0] = __floats2half2_rn(v.x, v.y);
    d[1] = __floats2half2_rn(v.z, v.w);
}

// ---------------- batched weight transpose -> half: dst[b][n][k] = half(src[b][k][n]) ----
__global__ void transpose_half_kernel(const float* __restrict__ src, __half* __restrict__ dst,
                                      int K, int N) {
    __shared__ float tile[32][33];
    const size_t boff = (size_t)blockIdx.z * K * N;
    const int kb = blockIdx.y * 32, nb = blockIdx.x * 32;
    const int tx = threadIdx.x, ty = threadIdx.y;
#pragma unroll
    for (int dy = 0; dy < 32; dy += 8) {
        const int k = kb + ty + dy, n = nb + tx;
        if (k < K && n < N) tile[ty + dy][tx] = src[boff + (size_t)k * N + n];
    }
    __syncthreads();
#pragma unroll
    for (int dy = 0; dy < 32; dy += 8) {
        const int n = nb + ty + dy, k = kb + tx;
        if (n < N && k < K) dst[boff + (size_t)n * K + k] = __float2half_rn(tile[tx][ty + dy]);
    }
}

// ---------------- triplet tmp2 (half in, half out) ----------------
__global__ void triplet_tmp2_kernel(const __half* __restrict__ down,
                                    const int* __restrict__ id3_ba,
                                    const float* __restrict__ sph,
                                    const float* __restrict__ rbfw1,
                                    __half* __restrict__ t2)
{
    __shared__ int   sIdx[256];
    __shared__ float sS[16 * 112];
    __shared__ float sR[16 * 112];

    const int tid = threadIdx.x;
    const int e0 = blockIdx.x * 16;

    sIdx[tid] = id3_ba[(size_t)e0 * 16 + tid];
    for (int r = tid; r < 16 * 112; r += 256) {
        sS[r] = sph  [(size_t)e0 * 112 + r];
        sR[r] = rbfw1[(size_t)e0 * 112 + r];
    }
    __syncthreads();

    const int team = tid >> 4;
    const int j = tid & 15;
    const int edge = e0 + team;

    float4 G[16];
#pragma unroll
    for (int k = 0; k < 16; k++) {
        const int row = sIdx[team * 16 + k];
        const __half2* dp = (const __half2*)(down + (size_t)row * 64 + j * 4);
        float2 lo = __half22float2(dp[0]);
        float2 hi = __half22float2(dp[1]);
        G[k] = make_float4(lo.x, lo.y, hi.x, hi.y);
    }

    float4 t1[7];
#pragma unroll
    for (int s = 0; s < 7; s++) {
        float4 a = make_float4(0.f, 0.f, 0.f, 0.f);
#pragma unroll
        for (int k = 0; k < 16; k++) {
            const float f = sS[team * 112 + s * 16 + k];
            a.x = fmaf(f, G[k].x, a.x); a.y = fmaf(f, G[k].y, a.y);
            a.z = fmaf(f, G[k].z, a.z); a.w = fmaf(f, G[k].w, a.w);
        }
        t1[s] = a;
    }

#pragma unroll
    for (int i = 0; i < 16; i++) {
        float4 a = make_float4(0.f, 0.f, 0.f, 0.f);
#pragma unroll
        for (int s = 0; s < 7; s++) {
            const float f = sR[team * 112 + i * 7 + s];
            a.x = fmaf(f, t1[s].x, a.x); a.y = fmaf(f, t1[s].y, a.y);
            a.z = fmaf(f, t1[s].z, a.z); a.w = fmaf(f, t1[s].w, a.w);
        }
        __half2* out = (__half2*)(t2 + (size_t)edge * 1024 + i * 64 + j * 4);
        out[0] = __floats2half2_rn(a.x, a.y);
        out[1] = __floats2half2_rn(a.z, a.w);
    }
}

// W_bil[e,i,o] -> WBPh[o][i*64+e]  ([64][1024] half, K-major)
__global__ void permute_wbil_kernel(const float* __restrict__ wb, __half* __restrict__ out) {
    const int idx = blockIdx.x * blockDim.x + threadIdx.x;
    const int o = idx & 63;
    const int i = (idx >> 6) & 15;
    const int e = idx >> 10;
    out[(size_t)o * 1024 + i * 64 + e] = __float2half_rn(wb[((size_t)(e * 16 + i)) * 64 + o]);
}

// x = (xca_skip + (up + ac[id_swap])*c)*c  -> fp32 XCA + half XCAh
__global__ void combine_x_kernel(float* xca, __half* xcah, const float* __restrict__ up,
                                 const float* __restrict__ ac, const int* __restrict__ id_swap) {
    const int idx = blockIdx.x * blockDim.x + threadIdx.x;
    const int e = idx >> 7;
    const int c = idx & 127;
    const int es = id_swap[e];
    float4 a = ((const float4*)up)[idx];
    float4 b = ((const float4*)ac)[(size_t)es * 128 + c];
    float4 x = ((float4*)xca)[idx];
    x.x = (x.x + (a.x + b.x) * INV_SQRT2) * INV_SQRT2;
    x.y = (x.y + (a.y + b.y) * INV_SQRT2) * INV_SQRT2;
    x.z = (x.z + (a.z + b.z) * INV_SQRT2) * INV_SQRT2;
    x.w = (x.w + (a.w + b.w) * INV_SQRT2) * INV_SQRT2;
    ((float4*)xca)[idx] = x;
    __half2* xh = (__half2*)xcah + 2 * idx;
    xh[0] = __floats2half2_rn(x.x, x.y);
    xh[1] = __floats2half2_rn(x.z, x.w);
}

// segment-sum: out[idx_t[e]] += m[e]*r2[e]
__global__ void scatter_atoms_kernel(const float* __restrict__ m, const float* __restrict__ r2,
                                     const int* __restrict__ idx_t, float* out) {
    const int idx = blockIdx.x * blockDim.x + threadIdx.x;
    const int e = idx >> 7;
    const int c = idx & 127;
    const int t = idx_t[e];
    float4 a = ((const float4*)m)[idx];
    float4 b = ((const float4*)r2)[idx];
    float* dst = out + (size_t)t * 512 + c * 4;
    atomicAdd(dst + 0, a.x * b.x);
    atomicAdd(dst + 1, a.y * b.y);
    atomicAdd(dst + 2, a.z * b.z);
    atomicAdd(dst + 3, a.w * b.w);
}

// ---------------- host orchestration ----------------
static void run_gemm(const __half* A, const __half* Bt, float* C, int M, int N, int K, int flags,
                     __half* Ct = nullptr,
                     const float* E = nullptr,
                     const float* Ad1 = nullptr, float c1 = 1.f,
                     const float* Ad2 = nullptr, float c2 = 1.f,
                     const __half* Hg = nullptr, const int* isx = nullptr,
                     const int* itx = nullptr, const __half* Mg = nullptr)
{
    static bool attr_set = false;
    if (!attr_set) {
        cudaFuncSetAttribute(mma_gemm_kernel, cudaFuncAttributeMaxDynamicSharedMemorySize, SMEM_DYN);
        attr_set = true;
    }
    dim3 grid((N + 127) / 128, (M + 127) / 128);
    mma_gemm_kernel<<<grid, 256, SMEM_DYN>>>(A, Bt, C, Ct, M, N, K, flags,
                                             E, Ad1, c1, Ad2, c2, Hg, isx, itx, Mg);
}
static void run_conv(const float* src, __half* dst, size_t n) {
    const int n4 = (int)(n / 4);
    conv_half_kernel<<<(n4 + 255) / 256, 256>>>(src, dst, n4);
}
static void run_transpose(const float* src, __half* dst, int K, int N, int batch = 1) {
    dim3 grid((N + 31) / 32, (K + 31) / 32, batch);
    transpose_half_kernel<<<grid, dim3(32, 8)>>>(src, dst, K, N);
}

extern "C" void kernel_launch(void* const* d_in, const int* in_sizes, int n_in,
                              void* d_out, int out_size)
{
    const float* h_in    = (const float*)d_in[0];
    const float* m_in    = (const float*)d_in[1];
    const float* rbf3    = (const float*)d_in[2];
    const float* rbf_w1  = (const float*)d_in[3];
    const float* sph     = (const float*)d_in[4];
    const float* rbf_h   = (const float*)d_in[5];
    const int*   id3_ba  = (const int*)d_in[6];
    const int*   id_swap = (const int*)d_in[9];
    const int*   idx_s   = (const int*)d_in[10];
    const int*   idx_t   = (const int*)d_in[11];
    const float* W_dense_ca = (const float*)d_in[12];
    const float* W_ba    = (const float*)d_in[13];
    const float* W_rbf3  = (const float*)d_in[14];
    const float* W_down  = (const float*)d_in[15];
    const float* W_bil   = (const float*)d_in[16];
    const float* W_up_ca = (const float*)d_in[17];
    const float* W_up_ac = (const float*)d_in[18];
    const float* W_bs    = (const float*)d_in[19];
    const float* W_as    = (const float*)d_in[20];
    const float* W_au_rbf= (const float*)d_in[21];
    const float* W_au_d1 = (const float*)d_in[22];
    const float* W_au_res= (const float*)d_in[23];
    const float* W_cat   = (const float*)d_in[24];
    const float* W_res_m = (const float*)d_in[25];

    float* pool = nullptr;
    cudaGetSymbolAddress((void**)&pool, g_pool);
    float*  XCA  = pool + OFF_XCA;
    float*  TMP  = pool + OFF_TMP;
    float*  UP   = pool + OFF_UP;
    float*  Mb   = pool + OFF_MB;
    float*  A1   = pool + OFF_A1;
    float*  A2   = pool + OFF_A2;
    __half* Mh   = (__half*)(pool + OFF_MH);
    __half* TMPh = (__half*)(pool + OFF_TMPH);
    __half* XCAh = (__half*)(pool + OFF_XCAH);
    __half* Mbh  = (__half*)(pool + OFF_MBH);
    __half* DWNh = (__half*)(pool + OFF_DWNH);
    __half* XBh  = (__half*)(pool + OFF_XBH);
    __half* T2h  = (__half*)(pool + OFF_T2H);
    __half* R3h  = (__half*)(pool + OFF_R3H);
    __half* RHh  = (__half*)(pool + OFF_RHH);
    __half* A1h  = (__half*)(pool + OFF_A1H);
    __half* A2h  = (__half*)(pool + OFF_A2H);
    __half* A3h  = (__half*)(pool + OFF_A3H);
    __half* OHh  = (__half*)(pool + OFF_OHH);
    __half* WH   = (__half*)(pool + OFF_WTSH);

    const size_t W2 = (size_t)DDg * DDg;
    __half* Wh_dense_ca = WH;            size_t woff = W2;
    __half* Wh_ba       = WH + woff;     woff += W2;
    __half* Wh_rbf3     = WH + woff;     woff += (size_t)DDg * 16;
    __half* Wh_down     = WH + woff;     woff += (size_t)DTg * DDg;
    __half* Wh_up_ca    = WH + woff;     woff += (size_t)DDg * DTg;
    __half* Wh_up_ac    = WH + woff;     woff += (size_t)DDg * DTg;
    __half* Wh_bs       = WH + woff;     woff += 2 * W2;
    __half* Wh_as       = WH + woff;     woff += 4 * W2;
    __half* Wh_au_rbf   = WH + woff;     woff += (size_t)DDg * 16;
    __half* Wh_au_d1    = WH + woff;     woff += W2;
    __half* Wh_au_res   = WH + woff;     woff += 6 * W2;
    __half* Wh_cat      = WH + woff;     woff += 3 * W2;
    __half* Wh_res_m    = WH + woff;     woff += 2 * W2;
    __half* WBPh        = WH + woff;     woff += (size_t)DTg * 1024;

    float* OUT_H = (float*)d_out;
    float* OUT_M = (float*)d_out + NA512;

    const float C = INV_SQRT2;

    // ---- pre-conversions ----
    run_conv(m_in, Mh, NE512);
    run_conv(rbf3, R3h, NE16);
    run_conv(rbf_h, RHh, NE16);
    run_transpose(W_dense_ca, Wh_dense_ca, DDg, DDg);
    run_transpose(W_ba, Wh_ba, DDg, DDg);
    run_transpose(W_rbf3, Wh_rbf3, 16, DDg);
    run_transpose(W_down, Wh_down, DDg, DTg);
    run_transpose(W_up_ca, Wh_up_ca, DTg, DDg);
    run_transpose(W_up_ac, Wh_up_ac, DTg, DDg);
    run_transpose(W_bs, Wh_bs, DDg, DDg, 2);
    run_transpose(W_as, Wh_as, DDg, DDg, 4);
    run_transpose(W_au_rbf, Wh_au_rbf, 16, DDg);
    run_transpose(W_au_d1, Wh_au_d1, DDg, DDg);
    run_transpose(W_au_res, Wh_au_res, DDg, DDg, 6);
    run_transpose(W_cat, Wh_cat, 3 * DDg, DDg);
    run_transpose(W_res_m, Wh_res_m, DDg, DDg, 2);
    permute_wbil_kernel<<<(NCBF * DTg * DTg) / 256, 256>>>(W_bil, WBPh);

    // ---- pipeline ----
    run_gemm(R3h, Wh_rbf3, TMP, NEg, DDg, 16, 0);
    run_gemm(Mh, Wh_ba, nullptr, NEg, DDg, DDg, F_ACT | F_MUL | F_HALF | F_NOF32,
             TMPh, TMP);
    run_gemm(TMPh, Wh_down, nullptr, NEg, DTg, DDg, F_ACT | F_HALF | F_NOF32, DWNh);
    run_gemm(Mh, Wh_dense_ca, XCA, NEg, DDg, DDg, F_ACT);

    triplet_tmp2_kernel<<<NEg / 16, 256>>>(DWNh, id3_ba, sph, rbf_w1, T2h);
    run_gemm(T2h, WBPh, nullptr, NEg, DTg, NCBF * DTg, F_HALF | F_NOF32, XBh);

    run_gemm(XBh, Wh_up_ca, UP, NEg, DDg, DTg, F_ACT);
    run_gemm(XBh, Wh_up_ac, TMP, NEg, DDg, DTg, F_ACT);
    combine_x_kernel<<<(NEg * 128) / 256, 256>>>(XCA, XCAh, UP, TMP, id_swap);

    run_gemm(XCAh, Wh_bs, nullptr, NEg, DDg, DDg, F_ACT | F_HALF | F_NOF32, TMPh);
    run_gemm(TMPh, Wh_bs + W2, Mb, NEg, DDg, DDg, F_ACT | F_ADD1 | F_ADD2 | F_HALF,
             Mbh, nullptr, XCA, C, m_in, C);

    run_gemm(Mbh, Wh_as + 0 * W2, nullptr, NEg, DDg, DDg, F_ACT | F_HALF | F_NOF32, TMPh);
    run_gemm(TMPh, Wh_as + 1 * W2, Mb, NEg, DDg, DDg, F_ACT | F_ADD1 | F_HALF,
             Mbh, nullptr, Mb, C);
    run_gemm(Mbh, Wh_as + 2 * W2, nullptr, NEg, DDg, DDg, F_ACT | F_HALF | F_NOF32, TMPh);
    run_gemm(TMPh, Wh_as + 3 * W2, Mb, NEg, DDg, DDg, F_ACT | F_ADD1 | F_HALF,
             Mbh, nullptr, Mb, C);

    run_gemm(RHh, Wh_au_rbf, UP, NEg, DDg, 16, 0);
    cudaMemsetAsync(A1, 0, NA512 * sizeof(float));
    scatter_atoms_kernel<<<(NEg * 128) / 256, 256>>>(Mb, UP, idx_t, A1);
    run_conv(A1, A1h, NA512);
    run_gemm(A1h, Wh_au_d1, A2, NAg, DDg, DDg, F_ACT | F_HALF, A2h);
    run_gemm(A2h, Wh_au_res + 0 * W2, nullptr, NAg, DDg, DDg, F_ACT | F_HALF | F_NOF32, A3h);
    run_gemm(A3h, Wh_au_res + 1 * W2, A2, NAg, DDg, DDg, F_ACT | F_ADD1 | F_HALF,
             A2h, nullptr, A2, C);
    run_gemm(A2h, Wh_au_res + 2 * W2, nullptr, NAg, DDg, DDg, F_ACT | F_HALF | F_NOF32, A3h);
    run_gemm(A3h, Wh_au_res + 3 * W2, A2, NAg, DDg, DDg, F_ACT | F_ADD1 | F_HALF,
             A2h, nullptr, A2, C);
    run_gemm(A2h, Wh_au_res + 4 * W2, nullptr, NAg, DDg, DDg, F_ACT | F_HALF | F_NOF32, A3h);
    run_gemm(A3h, Wh_au_res + 5 * W2, OUT_H, NAg, DDg, DDg,
             F_ACT | F_ADD1 | F_ADD2 | F_HALF, OHh, nullptr, A2, C, h_in, C);

    run_gemm(nullptr, Wh_cat, XCA, NEg, DDg, 3 * DDg, F_ACT | F_CAT | F_HALF,
             XCAh, nullptr, nullptr, 1.f, nullptr, 1.f, OHh, idx_s, idx_t, Mbh);

    run_gemm(XCAh, Wh_res_m, nullptr, NEg, DDg, DDg, F_ACT | F_HALF | F_NOF32, TMPh);
    run_gemm(TMPh, Wh_res_m + W2, OUT_M, NEg, DDg, DDg, F_ACT | F_ADD1 | F_ADD2,
             nullptr, nullptr, XCA, C, Mb, C);

    (void)in_sizes; (void)n_in; (void)out_size;
}